// round 13
// baseline (speedup 1.0000x reference)
#include <cuda_runtime.h>
#include <cuda_bf16.h>

#define N_ 384
#define D_ 256
#define H_ 8
#define DH_ 32
#define SCALE_ 0.17677669529663687f
#define L2E_ 1.4426950408889634f

typedef unsigned long long u64;

// ---------------- scratch (device globals; no allocation allowed) ----------
__device__ __align__(16) float g_Q [N_*H_*DH_];
__device__ __align__(16) float g_K [N_*H_*DH_];
__device__ __align__(16) float g_V [N_*H_*DH_];
__device__ __align__(16) float g_KQ[N_*H_*D_];   // [n][h][d] scale folded
__device__ __align__(16) float g_CK[N_*H_*D_];   // [n][h][d] scale folded
__device__ __align__(16) float g_PV[N_*H_*D_];   // [n][h][c]
__device__ __align__(16) float g_CB[N_*H_];
__device__ __align__(16) float g_SB[N_*H_];
__device__ __align__(16) float g_LS[N_*H_];
__device__ __align__(16) float g_SI[(size_t)N_*N_*H_];   // [i][j][h]
__device__ __align__(16) float g_P [(size_t)N_*N_*H_];   // [i][j][h] unnormalized
__device__ __align__(16) float g_AI[(size_t)N_*N_*H_];   // [j][i][h]  (transposed!)
__device__ __align__(16) float g_AJ[(size_t)N_*N_*H_];   // [j][i][h]

// ---------------- packed f32x2 helpers -------------------------------------
union F2U { float2 f; u64 u; };

__device__ __forceinline__ void dfma2(u64 &d, u64 a, u64 b) {
    asm("fma.rn.f32x2 %0, %1, %2, %0;" : "+l"(d) : "l"(a), "l"(b));
}
__device__ __forceinline__ u64 bcast2(float v) {
    F2U t; t.f.x = v; t.f.y = v; return t.u;
}
__device__ __forceinline__ float hsum2(u64 a) {
    F2U t; t.u = a; return t.f.x + t.f.y;
}
__device__ __forceinline__ u64 pack2f(float a, float b) {
    F2U t; t.f.x = a; t.f.y = b; return t.u;
}

// ---------------- P1: qx/kx/vx + cb/sb -------------------------------------
__global__ void kP1(const float* __restrict__ x,
                    const float* __restrict__ Wq_x, const float* __restrict__ bq_x,
                    const float* __restrict__ Wk_x, const float* __restrict__ bk_x,
                    const float* __restrict__ Wv_x, const float* __restrict__ bv_x,
                    const float* __restrict__ bk_e, const float* __restrict__ bq_e)
{
    __shared__ float x_s[8][D_];
    __shared__ float q_s[8][H_][DH_];
    __shared__ float k_s[8][H_][DH_];
    __shared__ float v_s[8][H_][DH_];
    const int t  = threadIdx.x;
    const int n0 = blockIdx.x * 8;

    #pragma unroll
    for (int n = 0; n < 8; n++) x_s[n][t] = x[(n0 + n) * D_ + t];
    __syncthreads();

    {
        const int h = t >> 5, k = t & 31;
        float aq[8], ak[8], av[8];
        const float bq = bq_x[h*DH_ + k], bk = bk_x[h*DH_ + k], bv = bv_x[h*DH_ + k];
        #pragma unroll
        for (int n = 0; n < 8; n++) { aq[n] = bq; ak[n] = bk; av[n] = bv; }
        for (int d = 0; d < D_; d++) {
            const float wq = Wq_x[(h*D_ + d)*DH_ + k];
            const float wk = Wk_x[(h*D_ + d)*DH_ + k];
            const float wv = Wv_x[(h*D_ + d)*DH_ + k];
            #pragma unroll
            for (int n = 0; n < 8; n++) {
                const float xv = x_s[n][d];
                aq[n] += xv * wq; ak[n] += xv * wk; av[n] += xv * wv;
            }
        }
        #pragma unroll
        for (int n = 0; n < 8; n++) {
            q_s[n][h][k] = aq[n]; k_s[n][h][k] = ak[n]; v_s[n][h][k] = av[n];
        }
    }
    __syncthreads();

    if (t < 64) {
        const int n = t >> 3, hh = t & 7;
        float cb = 0.f, sb = 0.f;
        #pragma unroll
        for (int kk = 0; kk < DH_; kk++) {
            cb += q_s[n][hh][kk] * bk_e[hh*DH_ + kk];
            sb += k_s[n][hh][kk] * bq_e[hh*DH_ + kk];
        }
        g_CB[(n0 + n)*H_ + hh] = cb * SCALE_;
        g_SB[(n0 + n)*H_ + hh] = sb * SCALE_;
    }

    const float* qs = (const float*)q_s;
    const float* ks = (const float*)k_s;
    const float* vs = (const float*)v_s;
    for (int idx = t; idx < 2048; idx += 256) {
        g_Q[n0*256 + idx] = qs[idx];
        g_K[n0*256 + idx] = ks[idx];
        g_V[n0*256 + idx] = vs[idx];
    }
}

// ---------------- P2: kq, ck, pv (smem-staged weights, conflict-free) -------
__global__ void __launch_bounds__(256) kP2(const float* __restrict__ Wk_e,
                                           const float* __restrict__ Wq_e,
                                           const float* __restrict__ WOe)
{
    __shared__ float w_s[256][33];      // padded: bank = (d + k) % 32
    __shared__ float q8[8][DH_], k8[8][DH_], v8[8][DH_];
    const int n0 = blockIdx.x * 8;
    const int hh = blockIdx.y;
    const int t  = threadIdx.x;

    {
        const int n = t >> 5, k = t & 31;
        q8[n][k] = g_Q[((n0 + n)*H_ + hh)*DH_ + k];
        k8[n][k] = g_K[((n0 + n)*H_ + hh)*DH_ + k];
        v8[n][k] = g_V[((n0 + n)*H_ + hh)*DH_ + k];
    }
    // stage Wk_e[hh] coalesced
    for (int idx = t; idx < 8192; idx += 256)
        w_s[idx >> 5][idx & 31] = Wk_e[hh*8192 + idx];
    __syncthreads();

    float akq[8], apv[8];
    #pragma unroll
    for (int n = 0; n < 8; n++) { akq[n] = 0.f; apv[n] = 0.f; }
    #pragma unroll 4
    for (int k = 0; k < DH_; k++) {
        const float wk = w_s[t][k];
        const float wo = WOe[(hh*DH_ + k)*D_ + t];   // coalesced
        #pragma unroll
        for (int n = 0; n < 8; n++) { akq[n] += wk * q8[n][k]; apv[n] += wo * v8[n][k]; }
    }
    __syncthreads();
    // stage Wq_e[hh]
    for (int idx = t; idx < 8192; idx += 256)
        w_s[idx >> 5][idx & 31] = Wq_e[hh*8192 + idx];
    __syncthreads();

    float ack[8];
    #pragma unroll
    for (int n = 0; n < 8; n++) ack[n] = 0.f;
    #pragma unroll 4
    for (int k = 0; k < DH_; k++) {
        const float wq = w_s[t][k];
        #pragma unroll
        for (int n = 0; n < 8; n++) ack[n] += wq * k8[n][k];
    }
    #pragma unroll
    for (int n = 0; n < 8; n++) {
        const int base = ((n0 + n)*H_ + hh)*D_ + t;
        g_KQ[base] = akq[n] * SCALE_;
        g_CK[base] = ack[n] * SCALE_;
        g_PV[base] = apv[n];
    }
}

// ---------------- S: row pass. Warp-per-edge, coalesced e, reg operands -----
// Block = row i, 192 thr (6 warps). Warp w handles j = w + 6m. Lane = channels.
__global__ void __launch_bounds__(192) kS(const float* __restrict__ e)
{
    __shared__ __align__(16) float wls[6][8];
    const int i = blockIdx.x;
    const int t = threadIdx.x;
    const int w = t >> 5, l = t & 31;

    // operand registers: lane l holds channels {4l..4l+3, 128+4l..128+4l+3}
    u64 kq[8][4], ck[8][4];
    #pragma unroll
    for (int h = 0; h < 8; h++) {
        const float4 a0 = *(const float4*)(g_KQ + (i*H_ + h)*D_ + 4*l);
        const float4 a1 = *(const float4*)(g_KQ + (i*H_ + h)*D_ + 128 + 4*l);
        kq[h][0] = pack2f(a0.x, a0.y); kq[h][1] = pack2f(a0.z, a0.w);
        kq[h][2] = pack2f(a1.x, a1.y); kq[h][3] = pack2f(a1.z, a1.w);
        const float4 b0 = *(const float4*)(g_CK + (i*H_ + h)*D_ + 4*l);
        const float4 b1 = *(const float4*)(g_CK + (i*H_ + h)*D_ + 128 + 4*l);
        ck[h][0] = pack2f(b0.x, b0.y); ck[h][1] = pack2f(b0.z, b0.w);
        ck[h][2] = pack2f(b1.x, b1.y); ck[h][3] = pack2f(b1.z, b1.w);
    }
    float cb[8], sb[8];
    {
        const float4 cA = *(const float4*)(g_CB + i*H_);
        const float4 cB = *(const float4*)(g_CB + i*H_ + 4);
        const float4 sA = *(const float4*)(g_SB + i*H_);
        const float4 sB = *(const float4*)(g_SB + i*H_ + 4);
        cb[0]=cA.x; cb[1]=cA.y; cb[2]=cA.z; cb[3]=cA.w;
        cb[4]=cB.x; cb[5]=cB.y; cb[6]=cB.z; cb[7]=cB.w;
        sb[0]=sA.x; sb[1]=sA.y; sb[2]=sA.z; sb[3]=sA.w;
        sb[4]=sB.x; sb[5]=sB.y; sb[6]=sB.z; sb[7]=sB.w;
    }
    float lsum[8];
    #pragma unroll
    for (int h = 0; h < 8; h++) lsum[h] = 0.f;

    const float* ebase = e + (size_t)i*N_*D_;

    #pragma unroll 1
    for (int it = 0; it < 32; it++) {
        const int j0 = w + 12*it, j1 = j0 + 6;
        // both rows' loads issued up front (coalesced LDG.128)
        const float4 ea0 = *(const float4*)(ebase + (size_t)j0*D_ + 4*l);
        const float4 eb0 = *(const float4*)(ebase + (size_t)j0*D_ + 128 + 4*l);
        const float4 ea1 = *(const float4*)(ebase + (size_t)j1*D_ + 4*l);
        const float4 eb1 = *(const float4*)(ebase + (size_t)j1*D_ + 128 + 4*l);

        #pragma unroll
        for (int u = 0; u < 2; u++) {
            const int j = u ? j1 : j0;
            u64 ev[4];
            if (u == 0) { ev[0]=pack2f(ea0.x,ea0.y); ev[1]=pack2f(ea0.z,ea0.w);
                          ev[2]=pack2f(eb0.x,eb0.y); ev[3]=pack2f(eb0.z,eb0.w); }
            else        { ev[0]=pack2f(ea1.x,ea1.y); ev[1]=pack2f(ea1.z,ea1.w);
                          ev[2]=pack2f(eb1.x,eb1.y); ev[3]=pack2f(eb1.z,eb1.w); }

            float dq[8], ds[8];
            #pragma unroll
            for (int h = 0; h < 8; h++) {
                u64 a = 0ull, b = 0ull;
                #pragma unroll
                for (int r = 0; r < 4; r++) { dfma2(a, ev[r], kq[h][r]); dfma2(b, ev[r], ck[h][r]); }
                dq[h] = hsum2(a); ds[h] = hsum2(b);
            }
            #pragma unroll
            for (int o = 16; o; o >>= 1) {
                #pragma unroll
                for (int h = 0; h < 8; h++) {
                    dq[h] += __shfl_xor_sync(0xffffffffu, dq[h], o);
                    ds[h] += __shfl_xor_sync(0xffffffffu, ds[h], o);
                }
            }
            if (l == 0) {
                float4* sip = (float4*)(g_SI + ((size_t)i*N_ + j)*H_);
                sip[0] = make_float4(ds[0]+sb[0], ds[1]+sb[1], ds[2]+sb[2], ds[3]+sb[3]);
                sip[1] = make_float4(ds[4]+sb[4], ds[5]+sb[5], ds[6]+sb[6], ds[7]+sb[7]);
                // scores O(+-5): exp2 cannot overflow; softmax shift-invariant.
                float p[8];
                #pragma unroll
                for (int h = 0; h < 8; h++) { p[h] = exp2f((dq[h]+cb[h])*L2E_); lsum[h] += p[h]; }
                float4* pp = (float4*)(g_P + ((size_t)i*N_ + j)*H_);
                pp[0] = make_float4(p[0], p[1], p[2], p[3]);
                pp[1] = make_float4(p[4], p[5], p[6], p[7]);
            }
        }
    }

    if (l == 0) {
        ((float4*)wls[w])[0] = make_float4(lsum[0], lsum[1], lsum[2], lsum[3]);
        ((float4*)wls[w])[1] = make_float4(lsum[4], lsum[5], lsum[6], lsum[7]);
    }
    __syncthreads();
    if (t < 8) {
        float s = 0.f;
        #pragma unroll
        for (int q = 0; q < 6; q++) s += wls[q][t];
        g_LS[i*H_ + t] = s;
    }
}

// ---------------- T: column pass. Warp-per-edge, sigmoid 2-way softmax ------
// Block = col j, 192 thr. Warp w handles i = w + 6m.
__global__ void __launch_bounds__(192) kT(const float* __restrict__ e)
{
    const int j = blockIdx.x;
    const int t = threadIdx.x;
    const int w = t >> 5, l = t & 31;

    u64 ck[8][4];
    #pragma unroll
    for (int h = 0; h < 8; h++) {
        const float4 b0 = *(const float4*)(g_CK + (j*H_ + h)*D_ + 4*l);
        const float4 b1 = *(const float4*)(g_CK + (j*H_ + h)*D_ + 128 + 4*l);
        ck[h][0] = pack2f(b0.x, b0.y); ck[h][1] = pack2f(b0.z, b0.w);
        ck[h][2] = pack2f(b1.x, b1.y); ck[h][3] = pack2f(b1.z, b1.w);
    }
    float sb[8];
    {
        const float4 sA = *(const float4*)(g_SB + j*H_);
        const float4 sB = *(const float4*)(g_SB + j*H_ + 4);
        sb[0]=sA.x; sb[1]=sA.y; sb[2]=sA.z; sb[3]=sA.w;
        sb[4]=sB.x; sb[5]=sB.y; sb[6]=sB.z; sb[7]=sB.w;
    }

    #pragma unroll 1
    for (int it = 0; it < 32; it++) {
        const int i0 = w + 12*it, i1 = i0 + 6;
        const float4 ea0 = *(const float4*)(e + ((size_t)i0*N_ + j)*D_ + 4*l);
        const float4 eb0 = *(const float4*)(e + ((size_t)i0*N_ + j)*D_ + 128 + 4*l);
        const float4 ea1 = *(const float4*)(e + ((size_t)i1*N_ + j)*D_ + 4*l);
        const float4 eb1 = *(const float4*)(e + ((size_t)i1*N_ + j)*D_ + 128 + 4*l);

        #pragma unroll
        for (int u = 0; u < 2; u++) {
            const int i = u ? i1 : i0;
            u64 ev[4];
            if (u == 0) { ev[0]=pack2f(ea0.x,ea0.y); ev[1]=pack2f(ea0.z,ea0.w);
                          ev[2]=pack2f(eb0.x,eb0.y); ev[3]=pack2f(eb0.z,eb0.w); }
            else        { ev[0]=pack2f(ea1.x,ea1.y); ev[1]=pack2f(ea1.z,ea1.w);
                          ev[2]=pack2f(eb1.x,eb1.y); ev[3]=pack2f(eb1.z,eb1.w); }

            float ds[8];
            #pragma unroll
            for (int h = 0; h < 8; h++) {
                u64 b = 0ull;
                #pragma unroll
                for (int r = 0; r < 4; r++) dfma2(b, ev[r], ck[h][r]);
                ds[h] = hsum2(b);
            }
            #pragma unroll
            for (int o = 16; o; o >>= 1) {
                #pragma unroll
                for (int h = 0; h < 8; h++)
                    ds[h] += __shfl_xor_sync(0xffffffffu, ds[h], o);
            }
            if (l == 0) {
                const float4 sA = *(const float4*)(g_SI + ((size_t)i*N_ + j)*H_);
                const float4 sB = *(const float4*)(g_SI + ((size_t)i*N_ + j)*H_ + 4);
                const float si[8] = {sA.x, sA.y, sA.z, sA.w, sB.x, sB.y, sB.z, sB.w};
                float ai[8], aj[8];
                #pragma unroll
                for (int h = 0; h < 8; h++) {
                    // ai = ei/(ei+ej) = 1/(1+exp(sj-si))  (sigmoid form)
                    const float x = exp2f((ds[h] + sb[h] - si[h]) * L2E_);
                    ai[h] = __fdividef(1.f, 1.f + x);
                    aj[h] = 1.f - ai[h];
                }
                float4* aip = (float4*)(g_AI + ((size_t)j*N_ + i)*H_);
                aip[0] = make_float4(ai[0], ai[1], ai[2], ai[3]);
                aip[1] = make_float4(ai[4], ai[5], ai[6], ai[7]);
                float4* ajp = (float4*)(g_AJ + ((size_t)j*N_ + i)*H_);
                ajp[0] = make_float4(aj[0], aj[1], aj[2], aj[3]);
                ajp[1] = make_float4(aj[4], aj[5], aj[6], aj[7]);
            }
        }
    }
}

// ---------------- E: eout = sum_h ai*pv_i + aj*pv_j + bOe -------------------
__global__ void __launch_bounds__(256) kE(const float* __restrict__ bOe,
                                          float* __restrict__ eout)
{
    const int i0 = blockIdx.x * 8;
    const int t  = threadIdx.x;
    const int tt = t & 127, ih = t >> 7;
    const int cp = 2 * tt;

    u64 pvi[4][H_];
    #pragma unroll
    for (int q = 0; q < 4; q++)
        #pragma unroll
        for (int h = 0; h < H_; h++)
            pvi[q][h] = *(const u64*)(g_PV + ((size_t)(i0 + ih*4 + q)*H_ + h)*D_ + cp);
    const u64 bo = *(const u64*)(bOe + cp);

    const int j0 = blockIdx.y * 96;
    for (int j = j0; j < j0 + 96; j++) {
        u64 pvj[H_];
        #pragma unroll
        for (int h = 0; h < H_; h++)
            pvj[h] = *(const u64*)(g_PV + ((size_t)j*H_ + h)*D_ + cp);
        #pragma unroll
        for (int q = 0; q < 4; q++) {
            const int irow = i0 + ih*4 + q;
            const float4 aiA = *(const float4*)(g_AI + ((size_t)j*N_ + irow)*H_);
            const float4 aiB = *(const float4*)(g_AI + ((size_t)j*N_ + irow)*H_ + 4);
            const float4 ajA = *(const float4*)(g_AJ + ((size_t)j*N_ + irow)*H_);
            const float4 ajB = *(const float4*)(g_AJ + ((size_t)j*N_ + irow)*H_ + 4);
            const float ai8[8] = {aiA.x, aiA.y, aiA.z, aiA.w, aiB.x, aiB.y, aiB.z, aiB.w};
            const float aj8[8] = {ajA.x, ajA.y, ajA.z, ajA.w, ajB.x, ajB.y, ajB.z, ajB.w};
            u64 acc = bo;
            #pragma unroll
            for (int h = 0; h < H_; h++) {
                dfma2(acc, bcast2(ai8[h]), pvi[q][h]);
                dfma2(acc, bcast2(aj8[h]), pvj[h]);
            }
            *(u64*)(eout + ((size_t)irow*N_ + j)*D_ + cp) = acc;
        }
    }
}

// ---------------- WF: we recompute + x projections (one node per block) -----
__global__ void __launch_bounds__(256) kWF(const float* __restrict__ e,
                                           const float* __restrict__ Wv_e,
                                           const float* __restrict__ bv_e,
                                           const float* __restrict__ WOx,
                                           const float* __restrict__ bOx,
                                           float* __restrict__ xout)
{
    __shared__ float p_s[N_*H_];
    __shared__ float ls_s[H_];
    __shared__ float we_s[H_][D_];
    __shared__ float xh_s[D_];
    const int i = blockIdx.x;
    const int t = threadIdx.x;

    {
        const float4* src = (const float4*)(g_P + (size_t)i*N_*H_);
        float4* dst = (float4*)p_s;
        for (int idx = t; idx < N_*H_/4; idx += 256) dst[idx] = src[idx];
    }
    if (t < H_) ls_s[t] = g_LS[i*H_ + t];
    __syncthreads();

    float we[H_];
    #pragma unroll
    for (int h = 0; h < H_; h++) we[h] = 0.f;

    const float* erow = e + (size_t)i*N_*D_ + t;
    #pragma unroll 4
    for (int j = 0; j < N_; j++) {
        const float ev = erow[(size_t)j*D_];
        const float4 pA = *(const float4*)&p_s[j*H_];
        const float4 pB = *(const float4*)&p_s[j*H_ + 4];
        we[0] += pA.x*ev; we[1] += pA.y*ev; we[2] += pA.z*ev; we[3] += pA.w*ev;
        we[4] += pB.x*ev; we[5] += pB.y*ev; we[6] += pB.z*ev; we[7] += pB.w*ev;
    }
    #pragma unroll
    for (int h = 0; h < H_; h++)
        we_s[h][t] = we[h] * __fdividef(1.f, ls_s[h]);
    __syncthreads();

    const int h = t >> 5, k = t & 31;
    float acc = bv_e[h*DH_ + k];
    #pragma unroll 4
    for (int d = 0; d < D_; d++)
        acc += we_s[h][d] * Wv_e[(h*D_ + d)*DH_ + k];
    xh_s[t] = acc;
    __syncthreads();

    float o = bOx[t];
    #pragma unroll 4
    for (int u = 0; u < D_; u++)
        o += xh_s[u] * WOx[u*D_ + t];
    xout[i*D_ + t] = o;
}

// ---------------- launcher ---------------------------------------------------
extern "C" void kernel_launch(void* const* d_in, const int* in_sizes, int n_in,
                              void* d_out, int out_size)
{
    const float* x    = (const float*)d_in[0];
    const float* e    = (const float*)d_in[1];
    const float* Wq_x = (const float*)d_in[2];
    const float* bq_x = (const float*)d_in[3];
    const float* Wk_e = (const float*)d_in[4];
    const float* bk_e = (const float*)d_in[5];
    const float* Wv_e = (const float*)d_in[6];
    const float* bv_e = (const float*)d_in[7];
    const float* Wq_e = (const float*)d_in[8];
    const float* bq_e = (const float*)d_in[9];
    const float* Wk_x = (const float*)d_in[10];
    const float* bk_x = (const float*)d_in[11];
    const float* Wv_x = (const float*)d_in[12];
    const float* bv_x = (const float*)d_in[13];
    const float* WOx  = (const float*)d_in[14];
    const float* bOx  = (const float*)d_in[15];
    const float* WOe  = (const float*)d_in[16];
    const float* bOe  = (const float*)d_in[17];

    float* xout = (float*)d_out;                 // [384,256]
    float* eout = (float*)d_out + N_*D_;         // [384,384,256]

    kP1<<<48, 256>>>(x, Wq_x, bq_x, Wk_x, bk_x, Wv_x, bv_x, bk_e, bq_e);
    kP2<<<dim3(48, 8), 256>>>(Wk_e, Wq_e, WOe);
    kS <<<N_, 192>>>(e);
    kT <<<N_, 192>>>(e);
    kE <<<dim3(48, 4), 256>>>(bOe, eout);
    kWF<<<N_, 256>>>(e, Wv_e, bv_e, WOx, bOx, xout);
}